// round 5
// baseline (speedup 1.0000x reference)
#include <cuda_runtime.h>
#include <cuda_bf16.h>
#include <math.h>

// Problem constants (fixed bench shapes)
#define BH    32            // B*H = 4*8
#define LSEQ  2048          // sequence length
#define DIM   64            // head dim
#define USEL  40            // u = U_part = 5*ceil(ln(2048)) = 40
#define NCH   8             // key chunks for split-softmax attention
#define CHK   (LSEQ/NCH)    // 256 keys per chunk
#define KVS   68            // KV smem row stride in attn
#define MCH   512           // m_kernel key-chunk size (smem 128 KB)
#define MQT   512           // m_kernel q-tile (4 tiles x 32 bh = 128 blocks)

// -------- scratch (device globals; no allocation allowed) --------
__device__ unsigned g_Mkey[BH * LSEQ];              // monotone-mapped sparsity keys
__device__ int   g_topk[BH * USEL];                 // selected query indices
__device__ float g_meanV[BH * DIM];                 // per-(b,h) mean of V
__device__ float g_pm[BH * NCH * USEL];             // partial softmax max
__device__ float g_pl[BH * NCH * USEL];             // partial softmax denom
__device__ float g_pacc[(size_t)BH * NCH * USEL * DIM]; // partial outputs
__device__ unsigned short g_sidx[LSEQ * USEL];      // samples sorted by chunk
__device__ unsigned g_soff[LSEQ];                   // packed chunk start offsets

__device__ __forceinline__ unsigned f2key(float x) {
    unsigned k = __float_as_uint(x);
    return (k & 0x80000000u) ? ~k : (k | 0x80000000u);
}

// ================= 1. mean of V per (b,h) =================
__global__ void mean_kernel(const float* __restrict__ V) {
    __shared__ float sb[256];
    int bh = blockIdx.x, t = threadIdx.x;
    int d = t & 63, part = t >> 6;
    const float* Vb = V + (size_t)bh * LSEQ * DIM;
    float s = 0.f;
    for (int l = part; l < LSEQ; l += 4)
        s += Vb[(size_t)l * DIM + d];
    sb[t] = s;
    __syncthreads();
    if (t < 64)
        g_meanV[bh * DIM + t] =
            (sb[t] + sb[t + 64] + sb[t + 128] + sb[t + 192]) * (1.0f / LSEQ);
}

// ================= 2. broadcast-fill output with meanV =================
__global__ void fill_kernel(float4* __restrict__ out) {
    int i = blockIdx.x * blockDim.x + threadIdx.x;   // over BH*LSEQ*16 float4s
    int bh = i >> 15;                                // LSEQ*16 = 32768
    int d4 = i & 15;
    out[i] = ((const float4*)g_meanV)[bh * 16 + d4];
}

// ================= 2b. bucket samples by key-chunk (shared across bh) ========
// One thread per q: counting sort of the 40 sample indices into 4 chunks of 512.
__global__ void sort_kernel(const int* __restrict__ idxs, int u) {
    int q = blockIdx.x * blockDim.x + threadIdx.x;
    if (q >= LSEQ) return;
    const int* ip = idxs + (size_t)q * u;
    int cnt[4] = {0, 0, 0, 0};
#pragma unroll
    for (int s = 0; s < USEL; s++)
        cnt[__ldg(ip + s) >> 9]++;
    int st1 = cnt[0];
    int st2 = st1 + cnt[1];
    int st3 = st2 + cnt[2];
    g_soff[q] = (unsigned)st1 | ((unsigned)st2 << 8) | ((unsigned)st3 << 16);
    int pos[4] = {0, st1, st2, st3};
#pragma unroll
    for (int s = 0; s < USEL; s++) {
        int ki = __ldg(ip + s);
        int c = ki >> 9;
        g_sidx[q * USEL + pos[c]++] = (unsigned short)ki;
    }
}

// ================= 3. M scores: chunked, smem-resident K =================
// Block = (q-tile of 512, bh), 1024 threads, 128 KB dynamic smem.
// Loops over 4 key chunks; stages each chunk once; every warp processes its
// 16 queries against the chunk's pre-bucketed samples via LDS (no K gather!).
// Per-lane online (max,sum) state persists across chunks; lane i holds q#i.
__global__ __launch_bounds__(1024, 1) void m_kernel(const float* __restrict__ Q,
                                                    const float* __restrict__ K) {
    extern __shared__ float Ks[];          // MCH x 64 floats = 128 KB
    int t = threadIdx.x, lane = t & 31, warp = t >> 5;
    int g = lane >> 3, h = lane & 7;
    int bh = blockIdx.y;
    int qlo = blockIdx.x * MQT;

    const float* Kb = K + (size_t)bh * LSEQ * DIM;
    float mxs = -1e30f, sms = 0.f;

    for (int c = 0; c < LSEQ / MCH; c++) {
        int cb = c * MCH;
        __syncthreads();   // previous chunk fully consumed
#pragma unroll
        for (int k = 0; k < (MCH * 16) / 1024; k++) {
            int f = t + k * 1024;
            int r = f >> 4, c4 = f & 15;
            ((float4*)Ks)[r * 16 + c4] =
                __ldg((const float4*)(Kb + (size_t)(cb + r) * DIM) + c4);
        }
        __syncthreads();

        for (int i = 0; i < 16; i++) {
            int q = qlo + warp * 16 + i;
            unsigned sw = g_soff[q];
            int lo = c ? (int)((sw >> (8 * (c - 1))) & 255u) : 0;
            int hi = (c < 3) ? (int)((sw >> (8 * c)) & 255u) : USEL;

            unsigned rp = ((const unsigned*)g_sidx)[q * (USEL / 2) + min(lane, USEL / 2 - 1)];
            const float4* Q4 = (const float4*)(Q + ((size_t)bh * LSEQ + q) * DIM);
            float4 qa = __ldg(Q4 + h);
            float4 qb = __ldg(Q4 + h + 8);

            float mxq = -1e30f, smq = 0.f;
            for (int p0 = lo; p0 < hi; p0 += 4) {
                int p = p0 + g;
                bool act = p < hi;
                int pp = act ? p : lo;
                unsigned w = __shfl_sync(0xFFFFFFFFu, rp, pp >> 1);
                int ki = (int)((w >> (16 * (pp & 1))) & 0xFFFFu);
                int kil = ki - cb;               // in [0, MCH)
                const float4* Kr = (const float4*)(Ks + kil * 64);
                float4 a0 = Kr[h], a1 = Kr[h + 8];
                float d = qa.x * a0.x;
                d = fmaf(qa.y, a0.y, d);
                d = fmaf(qa.z, a0.z, d);
                d = fmaf(qa.w, a0.w, d);
                d = fmaf(qb.x, a1.x, d);
                d = fmaf(qb.y, a1.y, d);
                d = fmaf(qb.z, a1.z, d);
                d = fmaf(qb.w, a1.w, d);
                d += __shfl_xor_sync(0xFFFFFFFFu, d, 1);
                d += __shfl_xor_sync(0xFFFFFFFFu, d, 2);
                d += __shfl_xor_sync(0xFFFFFFFFu, d, 4);
                if (act) { mxq = fmaxf(mxq, d); smq += d; }
            }
            // fold the 4 groups -> all lanes hold the q/chunk partial
            mxq = fmaxf(mxq, __shfl_xor_sync(0xFFFFFFFFu, mxq, 8));
            mxq = fmaxf(mxq, __shfl_xor_sync(0xFFFFFFFFu, mxq, 16));
            smq += __shfl_xor_sync(0xFFFFFFFFu, smq, 8);
            smq += __shfl_xor_sync(0xFFFFFFFFu, smq, 16);
            if (lane == i) { mxs = fmaxf(mxs, mxq); sms += smq; }
        }
    }

    if (lane < 16) {
        int q = qlo + warp * 16 + lane;
        g_Mkey[bh * LSEQ + q] = f2key(mxs - sms * (1.0f / LSEQ));
    }
}

// ================= 4. top-40 per (b,h) via radix select =================
__global__ __launch_bounds__(256) void topk_kernel() {
    __shared__ unsigned skeys[LSEQ];        // 8 KB
    __shared__ unsigned hist[256];
    __shared__ int ebuf[64];
    __shared__ unsigned s_prefix;
    __shared__ int s_remaining, s_cnt, s_eq;

    int bh = blockIdx.x, t = threadIdx.x;
    for (int i = t; i < LSEQ; i += 256)
        skeys[i] = g_Mkey[bh * LSEQ + i];
    if (t == 0) { s_prefix = 0u; s_remaining = USEL; s_cnt = 0; s_eq = 0; }
    __syncthreads();

    const unsigned himask[4] = {0u, 0xFF000000u, 0xFFFF0000u, 0xFFFFFF00u};
#pragma unroll
    for (int r = 0; r < 4; r++) {
        int shift = 24 - 8 * r;
        hist[t] = 0;
        __syncthreads();
        unsigned pfx = s_prefix;
        for (int i = t; i < LSEQ; i += 256) {
            unsigned k = skeys[i];
            if ((k & himask[r]) == pfx)
                atomicAdd(&hist[(k >> shift) & 255u], 1u);
        }
        __syncthreads();
        if (t < 32) {
            unsigned v[8], tot = 0;
#pragma unroll
            for (int c = 0; c < 8; c++) { v[c] = hist[t * 8 + c]; tot += v[c]; }
            unsigned suf = tot;
#pragma unroll
            for (int off = 1; off < 32; off <<= 1) {
                unsigned o = __shfl_down_sync(0xFFFFFFFFu, suf, off);
                if (t + off < 32) suf += o;
            }
            unsigned below = suf - tot;
            int rem = s_remaining;
#pragma unroll
            for (int c = 7; c >= 0; c--) {
                unsigned here = below + v[c];
                if ((int)here >= rem && (int)below < rem) {
                    s_prefix = pfx | ((unsigned)(t * 8 + c) << shift);
                    s_remaining = rem - (int)below;
                }
                below = here;
            }
        }
        __syncthreads();
    }

    unsigned T = s_prefix;
    int need_eq = s_remaining;

    for (int i = t; i < LSEQ; i += 256) {
        unsigned k = skeys[i];
        if (k > T) {
            int p = atomicAdd(&s_cnt, 1);
            g_topk[bh * USEL + p] = i;
        } else if (k == T) {
            int p = atomicAdd(&s_eq, 1);
            if (p < 64) ebuf[p] = i;
        }
    }
    __syncthreads();

    int cnt_gt = s_cnt, cnt_eq = s_eq;
    if (cnt_eq == need_eq) {
        if (t < cnt_eq)
            g_topk[bh * USEL + cnt_gt + t] = ebuf[t];
    } else if (t == 0) {
        if (cnt_eq <= 64) {
            for (int n = 0; n < need_eq; n++) {
                int bi = -1, bv = LSEQ;
                for (int j = 0; j < cnt_eq; j++)
                    if (ebuf[j] < bv) { bv = ebuf[j]; bi = j; }
                g_topk[bh * USEL + cnt_gt + n] = bv;
                ebuf[bi] = LSEQ;
            }
        } else {
            int n = 0;
            for (int i = 0; i < LSEQ && n < need_eq; i++)
                if (skeys[i] == T) g_topk[bh * USEL + cnt_gt + n++] = i;
        }
    }
}

// ================= 5. attention partials: block = (key-chunk, bh) =================
__global__ __launch_bounds__(256) void attn_kernel(const float* __restrict__ Q,
                                                   const float* __restrict__ K,
                                                   const float* __restrict__ V) {
    __shared__ float Qs[USEL * DIM];     // 10.0 KB (pre-scaled Q)
    __shared__ float KV[64 * KVS];       // 17.0 KB (K tile, then V tile)
    __shared__ float Pt[USEL * 64];      // 10.0 KB (scores -> probs)
    __shared__ float s_m[USEL], s_l[USEL], s_f[USEL], s_tm[USEL];

    int ch = blockIdx.x, bh = blockIdx.y;
    int t = threadIdx.x;
    int i = t >> 5, j = t & 31;

    const float* Kb = K + (size_t)bh * LSEQ * DIM;
    const float* Vb = V + (size_t)bh * LSEQ * DIM;

    for (int e = t; e < USEL * DIM; e += 256) {
        int q = e >> 6, d = e & 63;
        int qi = g_topk[bh * USEL + q];
        Qs[e] = Q[((size_t)bh * LSEQ + qi) * DIM + d] * 0.125f;
    }
    if (t < USEL) { s_m[t] = -1e30f; s_l[t] = 0.f; }
    float acc[5][2];
#pragma unroll
    for (int a = 0; a < 5; a++) { acc[a][0] = 0.f; acc[a][1] = 0.f; }
    __syncthreads();

    int kbase0 = ch * CHK;
    for (int kt = 0; kt < CHK / 64; kt++) {
        int kb = kbase0 + kt * 64;

#pragma unroll
        for (int rr = 0; rr < 4; rr++) {
            int f = t + rr * 256;
            int r = f >> 4, c4 = f & 15;
            float4 v = __ldg((const float4*)(Kb + (size_t)(kb + r) * DIM) + c4);
            *(float4*)&KV[r * KVS + c4 * 4] = v;
        }
        __syncthreads();

        float s[5][2];
#pragma unroll
        for (int a = 0; a < 5; a++) { s[a][0] = 0.f; s[a][1] = 0.f; }
#pragma unroll
        for (int d4 = 0; d4 < 16; d4++) {
            float4 k0 = *(const float4*)&KV[j * KVS + d4 * 4];
            float4 k1 = *(const float4*)&KV[(j + 32) * KVS + d4 * 4];
#pragma unroll
            for (int a = 0; a < 5; a++) {
                float4 qv = *(const float4*)&Qs[(i + 8 * a) * 64 + d4 * 4];
                float t0 = s[a][0];
                t0 = fmaf(qv.x, k0.x, t0);
                t0 = fmaf(qv.y, k0.y, t0);
                t0 = fmaf(qv.z, k0.z, t0);
                t0 = fmaf(qv.w, k0.w, t0);
                s[a][0] = t0;
                float t1 = s[a][1];
                t1 = fmaf(qv.x, k1.x, t1);
                t1 = fmaf(qv.y, k1.y, t1);
                t1 = fmaf(qv.z, k1.z, t1);
                t1 = fmaf(qv.w, k1.w, t1);
                s[a][1] = t1;
            }
        }
#pragma unroll
        for (int a = 0; a < 5; a++) {
            Pt[(i + 8 * a) * 64 + j]      = s[a][0];
            Pt[(i + 8 * a) * 64 + j + 32] = s[a][1];
        }
        __syncthreads();

        if (t < USEL) {
            float tm = -1e30f;
            for (int k = 0; k < 64; k++) tm = fmaxf(tm, Pt[t * 64 + k]);
            float mo = s_m[t];
            float mn = fmaxf(mo, tm);
            s_tm[t] = mn;
            s_f[t]  = __expf(mo - mn);
            s_m[t]  = mn;
        }
        __syncthreads();

#pragma unroll
        for (int rr = 0; rr < 4; rr++) {
            int f = t + rr * 256;
            int r = f >> 4, c4 = f & 15;
            float4 v = __ldg((const float4*)(Vb + (size_t)(kb + r) * DIM) + c4);
            *(float4*)&KV[r * KVS + c4 * 4] = v;
        }

        for (int e = t; e < USEL * 64; e += 256) {
            int q = e >> 6;
            Pt[e] = __expf(Pt[e] - s_tm[q]);
        }
#pragma unroll
        for (int a = 0; a < 5; a++) {
            float f = s_f[i + 8 * a];
            acc[a][0] *= f;
            acc[a][1] *= f;
        }
        __syncthreads();

        if (t < USEL) {
            float su = 0.f;
            for (int k = 0; k < 64; k++) su += Pt[t * 64 + k];
            s_l[t] = s_l[t] * s_f[t] + su;
        }

#pragma unroll
        for (int k4 = 0; k4 < 16; k4++) {
            int k = k4 * 4;
            float v00 = KV[(k + 0) * KVS + j];
            float v01 = KV[(k + 1) * KVS + j];
            float v02 = KV[(k + 2) * KVS + j];
            float v03 = KV[(k + 3) * KVS + j];
            float v10 = KV[(k + 0) * KVS + j + 32];
            float v11 = KV[(k + 1) * KVS + j + 32];
            float v12 = KV[(k + 2) * KVS + j + 32];
            float v13 = KV[(k + 3) * KVS + j + 32];
#pragma unroll
            for (int a = 0; a < 5; a++) {
                float4 p = *(const float4*)&Pt[(i + 8 * a) * 64 + k];
                float t0 = acc[a][0];
                t0 = fmaf(p.x, v00, t0);
                t0 = fmaf(p.y, v01, t0);
                t0 = fmaf(p.z, v02, t0);
                t0 = fmaf(p.w, v03, t0);
                acc[a][0] = t0;
                float t1 = acc[a][1];
                t1 = fmaf(p.x, v10, t1);
                t1 = fmaf(p.y, v11, t1);
                t1 = fmaf(p.z, v12, t1);
                t1 = fmaf(p.w, v13, t1);
                acc[a][1] = t1;
            }
        }
        __syncthreads();
    }

    float* pa = g_pacc + (size_t)(bh * NCH + ch) * USEL * DIM;
#pragma unroll
    for (int a = 0; a < 5; a++) {
        int q = i + 8 * a;
        pa[q * DIM + j]      = acc[a][0];
        pa[q * DIM + j + 32] = acc[a][1];
    }
    if (t < USEL) {
        g_pm[(bh * NCH + ch) * USEL + t] = s_m[t];
        g_pl[(bh * NCH + ch) * USEL + t] = s_l[t];
    }
}

// ================= 6. merge partials, scatter into output =================
__global__ void merge_kernel(float* __restrict__ out) {
    int u = blockIdx.x, bh = blockIdx.y, d = threadIdx.x;
    float M = -1e30f;
#pragma unroll
    for (int c = 0; c < NCH; c++)
        M = fmaxf(M, g_pm[(bh * NCH + c) * USEL + u]);
    float L = 0.f, o = 0.f;
#pragma unroll
    for (int c = 0; c < NCH; c++) {
        float w = __expf(g_pm[(bh * NCH + c) * USEL + u] - M);
        L += g_pl[(bh * NCH + c) * USEL + u] * w;
        o = fmaf(g_pacc[((size_t)(bh * NCH + c) * USEL + u) * DIM + d], w, o);
    }
    int qi = g_topk[bh * USEL + u];
    out[((size_t)bh * LSEQ + qi) * DIM + d] = o / L;
}

// ================= launcher =================
extern "C" void kernel_launch(void* const* d_in, const int* in_sizes, int n_in,
                              void* d_out, int out_size) {
    const float* Q    = (const float*)d_in[0];
    const float* K    = (const float*)d_in[1];
    const float* V    = (const float*)d_in[2];
    const int*   idxs = (const int*)d_in[3];
    float* out = (float*)d_out;
    int u = in_sizes[3] / LSEQ;   // 40

    // opt-in to 128 KB dynamic smem for m_kernel (idempotent, host-side)
    cudaFuncSetAttribute(m_kernel, cudaFuncAttributeMaxDynamicSharedMemorySize,
                         MCH * DIM * (int)sizeof(float));

    mean_kernel<<<BH, 256>>>(V);
    fill_kernel<<<(BH * LSEQ * 16) / 256, 256>>>((float4*)out);
    sort_kernel<<<LSEQ / 256, 256>>>(idxs, u);
    m_kernel<<<dim3(LSEQ / MQT, BH), 1024, MCH * DIM * sizeof(float)>>>(Q, K);
    topk_kernel<<<BH, 256>>>();
    attn_kernel<<<dim3(NCH, BH), 256>>>(Q, K, V);
    merge_kernel<<<dim3(USEL, BH), 64>>>(out);
}

// round 6
// speedup vs baseline: 1.1026x; 1.1026x over previous
#include <cuda_runtime.h>
#include <cuda_bf16.h>
#include <math.h>

// Problem constants (fixed bench shapes)
#define BH    32            // B*H = 4*8
#define LSEQ  2048          // sequence length
#define DIM   64            // head dim
#define USEL  40            // u = U_part = 5*ceil(ln(2048)) = 40
#define NCH   8             // key chunks for split-softmax attention
#define CHK   (LSEQ/NCH)    // 256 keys per chunk
#define KVS   68            // padded smem row stride (bank-conflict-free)
#define MCH   512           // m_kernel key-chunk size
#define MQT   512           // m_kernel q-tile (4 tiles x 32 bh = 128 blocks)

#define M_SMEM  (MCH * KVS * 4)                      // 139,264 B
#define A_QS    0
#define A_KS    (USEL * DIM)                         // 2560
#define A_VS    (A_KS + 64 * KVS)                    // 2560 + 4352
#define A_PT    (A_VS + 64 * KVS)
#define A_SMEM  ((A_PT + 8 * 5 * 64) * 4)            // 55,296 B

// -------- scratch (device globals; no allocation allowed) --------
__device__ unsigned g_Mkey[BH * LSEQ];
__device__ int   g_topk[BH * USEL];
__device__ float g_meanV[BH * DIM];
__device__ float g_pm[BH * NCH * USEL];
__device__ float g_pl[BH * NCH * USEL];
__device__ float g_pacc[(size_t)BH * NCH * USEL * DIM];
__device__ unsigned short g_sidx[LSEQ * USEL];      // samples sorted by chunk
__device__ unsigned g_soff[LSEQ];                   // packed chunk start offsets

__device__ __forceinline__ unsigned f2key(float x) {
    unsigned k = __float_as_uint(x);
    return (k & 0x80000000u) ? ~k : (k | 0x80000000u);
}

// ================= 1. mean of V per (b,h) =================
__global__ void mean_kernel(const float* __restrict__ V) {
    __shared__ float sb[256];
    int bh = blockIdx.x, t = threadIdx.x;
    int d = t & 63, part = t >> 6;
    const float* Vb = V + (size_t)bh * LSEQ * DIM;
    float s = 0.f;
    for (int l = part; l < LSEQ; l += 4)
        s += Vb[(size_t)l * DIM + d];
    sb[t] = s;
    __syncthreads();
    if (t < 64)
        g_meanV[bh * DIM + t] =
            (sb[t] + sb[t + 64] + sb[t + 128] + sb[t + 192]) * (1.0f / LSEQ);
}

// ================= 2. broadcast-fill output with meanV =================
__global__ void fill_kernel(float4* __restrict__ out) {
    int i = blockIdx.x * blockDim.x + threadIdx.x;
    int bh = i >> 15;
    int d4 = i & 15;
    out[i] = ((const float4*)g_meanV)[bh * 16 + d4];
}

// ================= 2b. bucket samples by key-chunk (shared across bh) ========
__global__ void sort_kernel(const int* __restrict__ idxs, int u) {
    int q = blockIdx.x * blockDim.x + threadIdx.x;
    if (q >= LSEQ) return;
    const int* ip = idxs + (size_t)q * u;
    int cnt[4] = {0, 0, 0, 0};
#pragma unroll
    for (int s = 0; s < USEL; s++)
        cnt[__ldg(ip + s) >> 9]++;
    int st1 = cnt[0];
    int st2 = st1 + cnt[1];
    int st3 = st2 + cnt[2];
    g_soff[q] = (unsigned)st1 | ((unsigned)st2 << 8) | ((unsigned)st3 << 16);
    int pos[4] = {0, st1, st2, st3};
#pragma unroll
    for (int s = 0; s < USEL; s++) {
        int ki = __ldg(ip + s);
        int c = ki >> 9;
        g_sidx[q * USEL + pos[c]++] = (unsigned short)ki;
    }
}

// ================= 3. M scores: chunked, smem-resident K (PADDED stride) =====
// Block = (q-tile of 512, bh), 1024 threads, 139 KB dynamic smem.
// K rows stored at stride KVS=68 floats: group bank-shift = 4*(row mod 8),
// so 4 concurrent random-row reads rarely collide (avg degree ~1.4, was 4).
__global__ __launch_bounds__(1024, 1) void m_kernel(const float* __restrict__ Q,
                                                    const float* __restrict__ K) {
    extern __shared__ float Ks[];          // MCH x KVS floats
    int t = threadIdx.x, lane = t & 31, warp = t >> 5;
    int g = lane >> 3, h = lane & 7;
    int bh = blockIdx.y;
    int qlo = blockIdx.x * MQT;

    const float* Kb = K + (size_t)bh * LSEQ * DIM;
    float mxs = -1e30f, sms = 0.f;

    for (int c = 0; c < LSEQ / MCH; c++) {
        int cb = c * MCH;
        __syncthreads();   // previous chunk fully consumed
#pragma unroll
        for (int k = 0; k < (MCH * 16) / 1024; k++) {
            int f = t + k * 1024;
            int r = f >> 4, c4 = f & 15;
            ((float4*)Ks)[r * (KVS / 4) + c4] =
                __ldg((const float4*)(Kb + (size_t)(cb + r) * DIM) + c4);
        }
        __syncthreads();

        for (int i = 0; i < 16; i++) {
            int q = qlo + warp * 16 + i;
            unsigned sw = g_soff[q];
            int lo = c ? (int)((sw >> (8 * (c - 1))) & 255u) : 0;
            int hi = (c < 3) ? (int)((sw >> (8 * c)) & 255u) : USEL;

            unsigned rp = ((const unsigned*)g_sidx)[q * (USEL / 2) + min(lane, USEL / 2 - 1)];
            const float4* Q4 = (const float4*)(Q + ((size_t)bh * LSEQ + q) * DIM);
            float4 qa = __ldg(Q4 + h);
            float4 qb = __ldg(Q4 + h + 8);

            float mxq = -1e30f, smq = 0.f;
            for (int p0 = lo; p0 < hi; p0 += 4) {
                int p = p0 + g;
                bool act = p < hi;
                int pp = act ? p : lo;
                unsigned w = __shfl_sync(0xFFFFFFFFu, rp, pp >> 1);
                int ki = (int)((w >> (16 * (pp & 1))) & 0xFFFFu);
                int kil = ki - cb;               // in [0, MCH)
                const float4* Kr = (const float4*)(Ks + kil * KVS);
                float4 a0 = Kr[h], a1 = Kr[h + 8];
                float d = qa.x * a0.x;
                d = fmaf(qa.y, a0.y, d);
                d = fmaf(qa.z, a0.z, d);
                d = fmaf(qa.w, a0.w, d);
                d = fmaf(qb.x, a1.x, d);
                d = fmaf(qb.y, a1.y, d);
                d = fmaf(qb.z, a1.z, d);
                d = fmaf(qb.w, a1.w, d);
                d += __shfl_xor_sync(0xFFFFFFFFu, d, 1);
                d += __shfl_xor_sync(0xFFFFFFFFu, d, 2);
                d += __shfl_xor_sync(0xFFFFFFFFu, d, 4);
                if (act) { mxq = fmaxf(mxq, d); smq += d; }
            }
            mxq = fmaxf(mxq, __shfl_xor_sync(0xFFFFFFFFu, mxq, 8));
            mxq = fmaxf(mxq, __shfl_xor_sync(0xFFFFFFFFu, mxq, 16));
            smq += __shfl_xor_sync(0xFFFFFFFFu, smq, 8);
            smq += __shfl_xor_sync(0xFFFFFFFFu, smq, 16);
            if (lane == i) { mxs = fmaxf(mxs, mxq); sms += smq; }
        }
    }

    if (lane < 16) {
        int q = qlo + warp * 16 + lane;
        g_Mkey[bh * LSEQ + q] = f2key(mxs - sms * (1.0f / LSEQ));
    }
}

// ================= 4. top-40 per (b,h) via radix select =================
__global__ __launch_bounds__(256) void topk_kernel() {
    __shared__ unsigned skeys[LSEQ];
    __shared__ unsigned hist[256];
    __shared__ int ebuf[64];
    __shared__ unsigned s_prefix;
    __shared__ int s_remaining, s_cnt, s_eq;

    int bh = blockIdx.x, t = threadIdx.x;
    for (int i = t; i < LSEQ; i += 256)
        skeys[i] = g_Mkey[bh * LSEQ + i];
    if (t == 0) { s_prefix = 0u; s_remaining = USEL; s_cnt = 0; s_eq = 0; }
    __syncthreads();

    const unsigned himask[4] = {0u, 0xFF000000u, 0xFFFF0000u, 0xFFFFFF00u};
#pragma unroll
    for (int r = 0; r < 4; r++) {
        int shift = 24 - 8 * r;
        hist[t] = 0;
        __syncthreads();
        unsigned pfx = s_prefix;
        for (int i = t; i < LSEQ; i += 256) {
            unsigned k = skeys[i];
            if ((k & himask[r]) == pfx)
                atomicAdd(&hist[(k >> shift) & 255u], 1u);
        }
        __syncthreads();
        if (t < 32) {
            unsigned v[8], tot = 0;
#pragma unroll
            for (int c = 0; c < 8; c++) { v[c] = hist[t * 8 + c]; tot += v[c]; }
            unsigned suf = tot;
#pragma unroll
            for (int off = 1; off < 32; off <<= 1) {
                unsigned o = __shfl_down_sync(0xFFFFFFFFu, suf, off);
                if (t + off < 32) suf += o;
            }
            unsigned below = suf - tot;
            int rem = s_remaining;
#pragma unroll
            for (int c = 7; c >= 0; c--) {
                unsigned here = below + v[c];
                if ((int)here >= rem && (int)below < rem) {
                    s_prefix = pfx | ((unsigned)(t * 8 + c) << shift);
                    s_remaining = rem - (int)below;
                }
                below = here;
            }
        }
        __syncthreads();
    }

    unsigned T = s_prefix;
    int need_eq = s_remaining;

    for (int i = t; i < LSEQ; i += 256) {
        unsigned k = skeys[i];
        if (k > T) {
            int p = atomicAdd(&s_cnt, 1);
            g_topk[bh * USEL + p] = i;
        } else if (k == T) {
            int p = atomicAdd(&s_eq, 1);
            if (p < 64) ebuf[p] = i;
        }
    }
    __syncthreads();

    int cnt_gt = s_cnt, cnt_eq = s_eq;
    if (cnt_eq == need_eq) {
        if (t < cnt_eq)
            g_topk[bh * USEL + cnt_gt + t] = ebuf[t];
    } else if (t == 0) {
        if (cnt_eq <= 64) {
            for (int n = 0; n < need_eq; n++) {
                int bi = -1, bv = LSEQ;
                for (int j = 0; j < cnt_eq; j++)
                    if (ebuf[j] < bv) { bv = ebuf[j]; bi = j; }
                g_topk[bh * USEL + cnt_gt + n] = bv;
                ebuf[bi] = LSEQ;
            }
        } else {
            int n = 0;
            for (int i = 0; i < LSEQ && n < need_eq; i++)
                if (skeys[i] == T) g_topk[bh * USEL + cnt_gt + n++] = i;
        }
    }
}

// ================= 5. attention partials: register-resident softmax ==========
// Block (ch, bh), 256 threads. Warp i owns queries {i+8a}; lane j owns
// keys/dims {j, j+32}. Scores, softmax state, and probs all in registers;
// max/sum via 5-shuffle butterflies; probs round-trip a WARP-PRIVATE Pt
// (only __syncwarp). 2 __syncthreads per tile (was 6 + serial sections).
__global__ __launch_bounds__(256) void attn_kernel(const float* __restrict__ Q,
                                                   const float* __restrict__ K,
                                                   const float* __restrict__ V) {
    extern __shared__ float sm[];
    float* Qs = sm + A_QS;               // USEL*64, pre-scaled Q
    float* Ks = sm + A_KS;               // 64 x KVS
    float* Vs = sm + A_VS;               // 64 x KVS
    float* Pt = sm + A_PT;               // 8 warps x 5 x 64 (warp-private)

    int ch = blockIdx.x, bh = blockIdx.y;
    int t = threadIdx.x;
    int i = t >> 5, j = t & 31;

    const float* Kb = K + (size_t)bh * LSEQ * DIM;
    const float* Vb = V + (size_t)bh * LSEQ * DIM;

    for (int e = t; e < USEL * DIM; e += 256) {
        int q = e >> 6, d = e & 63;
        int qi = g_topk[bh * USEL + q];
        Qs[e] = Q[((size_t)bh * LSEQ + qi) * DIM + d] * 0.125f;
    }

    float m_[5], l_[5], acc[5][2];
#pragma unroll
    for (int a = 0; a < 5; a++) {
        m_[a] = -1e30f; l_[a] = 0.f; acc[a][0] = 0.f; acc[a][1] = 0.f;
    }

    int kbase0 = ch * CHK;
    for (int kt = 0; kt < CHK / 64; kt++) {
        int kb = kbase0 + kt * 64;
        __syncthreads();                       // prior tile fully consumed (covers Qs too)

        // stage K and V tiles (4 float4 each per thread)
#pragma unroll
        for (int rr = 0; rr < 4; rr++) {
            int f = t + rr * 256;
            int r = f >> 4, c4 = f & 15;
            *(float4*)&Ks[r * KVS + c4 * 4] =
                __ldg((const float4*)(Kb + (size_t)(kb + r) * DIM) + c4);
            *(float4*)&Vs[r * KVS + c4 * 4] =
                __ldg((const float4*)(Vb + (size_t)(kb + r) * DIM) + c4);
        }
        __syncthreads();

        // --- S = Qs @ K^T (registers) ---
        float s0[5], s1[5];
#pragma unroll
        for (int a = 0; a < 5; a++) { s0[a] = 0.f; s1[a] = 0.f; }
#pragma unroll
        for (int d4 = 0; d4 < 16; d4++) {
            float4 k0 = *(const float4*)&Ks[j * KVS + d4 * 4];
            float4 k1 = *(const float4*)&Ks[(j + 32) * KVS + d4 * 4];
#pragma unroll
            for (int a = 0; a < 5; a++) {
                float4 qv = *(const float4*)&Qs[(i + 8 * a) * 64 + d4 * 4];
                float u0 = s0[a];
                u0 = fmaf(qv.x, k0.x, u0);
                u0 = fmaf(qv.y, k0.y, u0);
                u0 = fmaf(qv.z, k0.z, u0);
                u0 = fmaf(qv.w, k0.w, u0);
                s0[a] = u0;
                float u1 = s1[a];
                u1 = fmaf(qv.x, k1.x, u1);
                u1 = fmaf(qv.y, k1.y, u1);
                u1 = fmaf(qv.z, k1.z, u1);
                u1 = fmaf(qv.w, k1.w, u1);
                s1[a] = u1;
            }
        }

        // --- online softmax in registers (butterflies converge all lanes) ---
#pragma unroll
        for (int a = 0; a < 5; a++) {
            float tm = fmaxf(s0[a], s1[a]);
#pragma unroll
            for (int o = 16; o; o >>= 1)
                tm = fmaxf(tm, __shfl_xor_sync(0xFFFFFFFFu, tm, o));
            float mn = fmaxf(m_[a], tm);
            float f  = __expf(m_[a] - mn);
            float p0 = __expf(s0[a] - mn);
            float p1 = __expf(s1[a] - mn);
            float su = p0 + p1;
#pragma unroll
            for (int o = 16; o; o >>= 1)
                su += __shfl_xor_sync(0xFFFFFFFFu, su, o);
            m_[a] = mn;
            l_[a] = l_[a] * f + su;
            acc[a][0] *= f;
            acc[a][1] *= f;
            Pt[(i * 5 + a) * 64 + j]      = p0;
            Pt[(i * 5 + a) * 64 + j + 32] = p1;
        }
        __syncwarp();                          // Pt is warp-private

        // --- acc += P @ V ---
#pragma unroll
        for (int k4 = 0; k4 < 16; k4++) {
            int k = k4 * 4;
            float v00 = Vs[(k + 0) * KVS + j];
            float v01 = Vs[(k + 1) * KVS + j];
            float v02 = Vs[(k + 2) * KVS + j];
            float v03 = Vs[(k + 3) * KVS + j];
            float v10 = Vs[(k + 0) * KVS + j + 32];
            float v11 = Vs[(k + 1) * KVS + j + 32];
            float v12 = Vs[(k + 2) * KVS + j + 32];
            float v13 = Vs[(k + 3) * KVS + j + 32];
#pragma unroll
            for (int a = 0; a < 5; a++) {
                float4 p = *(const float4*)&Pt[(i * 5 + a) * 64 + k];  // broadcast
                float u0 = acc[a][0];
                u0 = fmaf(p.x, v00, u0);
                u0 = fmaf(p.y, v01, u0);
                u0 = fmaf(p.z, v02, u0);
                u0 = fmaf(p.w, v03, u0);
                acc[a][0] = u0;
                float u1 = acc[a][1];
                u1 = fmaf(p.x, v10, u1);
                u1 = fmaf(p.y, v11, u1);
                u1 = fmaf(p.z, v12, u1);
                u1 = fmaf(p.w, v13, u1);
                acc[a][1] = u1;
            }
        }
    }

    float* pa = g_pacc + (size_t)(bh * NCH + ch) * USEL * DIM;
#pragma unroll
    for (int a = 0; a < 5; a++) {
        int q = i + 8 * a;
        pa[q * DIM + j]      = acc[a][0];
        pa[q * DIM + j + 32] = acc[a][1];
    }
    if (j == 0) {
#pragma unroll
        for (int a = 0; a < 5; a++) {
            g_pm[(bh * NCH + ch) * USEL + i + 8 * a] = m_[a];
            g_pl[(bh * NCH + ch) * USEL + i + 8 * a] = l_[a];
        }
    }
}

// ================= 6. merge partials, scatter into output =================
__global__ void merge_kernel(float* __restrict__ out) {
    int u = blockIdx.x, bh = blockIdx.y, d = threadIdx.x;
    float M = -1e30f;
#pragma unroll
    for (int c = 0; c < NCH; c++)
        M = fmaxf(M, g_pm[(bh * NCH + c) * USEL + u]);
    float L = 0.f, o = 0.f;
#pragma unroll
    for (int c = 0; c < NCH; c++) {
        float w = __expf(g_pm[(bh * NCH + c) * USEL + u] - M);
        L += g_pl[(bh * NCH + c) * USEL + u] * w;
        o = fmaf(g_pacc[((size_t)(bh * NCH + c) * USEL + u) * DIM + d], w, o);
    }
    int qi = g_topk[bh * USEL + u];
    out[((size_t)bh * LSEQ + qi) * DIM + d] = o / L;
}

// ================= launcher =================
extern "C" void kernel_launch(void* const* d_in, const int* in_sizes, int n_in,
                              void* d_out, int out_size) {
    const float* Q    = (const float*)d_in[0];
    const float* K    = (const float*)d_in[1];
    const float* V    = (const float*)d_in[2];
    const int*   idxs = (const int*)d_in[3];
    float* out = (float*)d_out;
    int u = in_sizes[3] / LSEQ;   // 40

    cudaFuncSetAttribute(m_kernel, cudaFuncAttributeMaxDynamicSharedMemorySize, M_SMEM);
    cudaFuncSetAttribute(attn_kernel, cudaFuncAttributeMaxDynamicSharedMemorySize, A_SMEM);

    mean_kernel<<<BH, 256>>>(V);
    fill_kernel<<<(BH * LSEQ * 16) / 256, 256>>>((float4*)out);
    sort_kernel<<<LSEQ / 256, 256>>>(idxs, u);
    m_kernel<<<dim3(LSEQ / MQT, BH), 1024, M_SMEM>>>(Q, K);
    topk_kernel<<<BH, 256>>>();
    attn_kernel<<<dim3(NCH, BH), 256, A_SMEM>>>(Q, K, V);
    merge_kernel<<<dim3(USEL, BH), 64>>>(out);
}

// round 7
// speedup vs baseline: 1.2145x; 1.1014x over previous
#include <cuda_runtime.h>
#include <cuda_bf16.h>
#include <math.h>

// Problem constants (fixed bench shapes)
#define BH    32            // B*H = 4*8
#define LSEQ  2048          // sequence length
#define DIM   64            // head dim
#define USEL  40            // u = U_part
#define NCH   32            // key chunks for split-softmax attention
#define CHK   (LSEQ/NCH)    // 64 keys per chunk (single tile per block)
#define KVS   68            // padded smem row stride for attn K/V tiles
#define MCH   512           // m_kernel key-chunk size (smem 128 KB)
#define MQT   256           // m_kernel q-tile (8 tiles x 32 bh = 256 blocks)

#define M_SMEM  (MCH * DIM * 4)                      // 131,072 B
#define A_QS    0
#define A_KS    (USEL * DIM)                         // 2560
#define A_VS    (A_KS + 64 * KVS)
#define A_PT    (A_VS + 64 * KVS)
#define A_SMEM  ((A_PT + 8 * 5 * 64) * 4)            // 55,296 B

// -------- scratch (device globals; no allocation allowed) --------
__device__ unsigned g_Mkey[BH * LSEQ];
__device__ int   g_topk[BH * USEL];
__device__ float g_meanV[BH * DIM];
__device__ float g_pm[BH * NCH * USEL];
__device__ float g_pl[BH * NCH * USEL];
__device__ float g_pacc[(size_t)BH * NCH * USEL * DIM];   // 10.5 MB
__device__ unsigned short g_sidx[LSEQ * USEL];      // samples sorted by chunk
__device__ unsigned g_soff[LSEQ];                   // packed chunk start offsets

__device__ __forceinline__ unsigned f2key(float x) {
    unsigned k = __float_as_uint(x);
    return (k & 0x80000000u) ? ~k : (k | 0x80000000u);
}

// ================= 1. mean of V per (b,h): vectorized =================
__global__ __launch_bounds__(1024) void mean_kernel(const float* __restrict__ V) {
    __shared__ float4 sb[64][16];
    int bh = blockIdx.x, t = threadIdx.x;
    int part = t >> 4, c4 = t & 15;
    const float4* Vb = (const float4*)(V + (size_t)bh * LSEQ * DIM);
    float4 s = make_float4(0.f, 0.f, 0.f, 0.f);
    for (int l = part; l < LSEQ; l += 64) {
        float4 v = __ldg(Vb + l * 16 + c4);
        s.x += v.x; s.y += v.y; s.z += v.z; s.w += v.w;
    }
    sb[part][c4] = s;
    __syncthreads();
#pragma unroll
    for (int o = 32; o; o >>= 1) {
        if (part < o) {
            float4 a = sb[part][c4], b = sb[part + o][c4];
            a.x += b.x; a.y += b.y; a.z += b.z; a.w += b.w;
            sb[part][c4] = a;
        }
        __syncthreads();
    }
    if (t < 16) {
        float4 a = sb[0][t];
        a.x *= (1.0f / LSEQ); a.y *= (1.0f / LSEQ);
        a.z *= (1.0f / LSEQ); a.w *= (1.0f / LSEQ);
        ((float4*)g_meanV)[bh * 16 + t] = a;
    }
}

// ================= 2. broadcast-fill output with meanV =================
__global__ void fill_kernel(float4* __restrict__ out) {
    int i = blockIdx.x * blockDim.x + threadIdx.x;
    int bh = i >> 15;
    int d4 = i & 15;
    out[i] = ((const float4*)g_meanV)[bh * 16 + d4];
}

// ================= 2b. bucket samples by key-chunk (shared across bh) ========
__global__ void sort_kernel(const int* __restrict__ idxs, int u) {
    int q = blockIdx.x * blockDim.x + threadIdx.x;
    if (q >= LSEQ) return;
    const int* ip = idxs + (size_t)q * u;
    int cnt[4] = {0, 0, 0, 0};
#pragma unroll
    for (int s = 0; s < USEL; s++)
        cnt[__ldg(ip + s) >> 9]++;
    int st1 = cnt[0];
    int st2 = st1 + cnt[1];
    int st3 = st2 + cnt[2];
    g_soff[q] = (unsigned)st1 | ((unsigned)st2 << 8) | ((unsigned)st3 << 16);
    int pos[4] = {0, st1, st2, st3};
#pragma unroll
    for (int s = 0; s < USEL; s++) {
        int ki = __ldg(ip + s);
        int c = ki >> 9;
        g_sidx[q * USEL + pos[c]++] = (unsigned short)ki;
    }
}

// ================= 3. M scores: chunked, smem-resident K =================
// Block = (q-tile of 256, bh), 1024 threads, 128 KB smem. Stride 64 floats
// (shift addressing; LDS.128 quarter-warp phases are conflict-free since each
// 8-lane group reads a contiguous 128B). Dot split into two 4-FMA chains.
__global__ __launch_bounds__(1024, 1) void m_kernel(const float* __restrict__ Q,
                                                    const float* __restrict__ K) {
    extern __shared__ float Ks[];          // MCH x 64 floats
    int t = threadIdx.x, lane = t & 31, warp = t >> 5;
    int g = lane >> 3, h = lane & 7;
    int bh = blockIdx.y;
    int qlo = blockIdx.x * MQT;

    const float* Kb = K + (size_t)bh * LSEQ * DIM;
    float mxs = -1e30f, sms = 0.f;

    for (int c = 0; c < LSEQ / MCH; c++) {
        int cb = c * MCH;
        __syncthreads();   // previous chunk fully consumed
#pragma unroll
        for (int k = 0; k < (MCH * 16) / 1024; k++) {
            int f = t + k * 1024;
            ((float4*)Ks)[f] = __ldg((const float4*)(Kb + (size_t)cb * DIM) + f);
        }
        __syncthreads();

        for (int i = 0; i < MQT / 32; i++) {          // 8 queries per warp
            int q = qlo + warp * (MQT / 32) + i;
            unsigned sw = g_soff[q];
            int lo = c ? (int)((sw >> (8 * (c - 1))) & 255u) : 0;
            int hi = (c < 3) ? (int)((sw >> (8 * c)) & 255u) : USEL;

            unsigned rp = ((const unsigned*)g_sidx)[q * (USEL / 2) + min(lane, USEL / 2 - 1)];
            const float4* Q4 = (const float4*)(Q + ((size_t)bh * LSEQ + q) * DIM);
            float4 qa = __ldg(Q4 + h);
            float4 qb = __ldg(Q4 + h + 8);

            float mxq = -1e30f, smq = 0.f;
            for (int p0 = lo; p0 < hi; p0 += 4) {
                int p = p0 + g;
                bool act = p < hi;
                int pp = act ? p : lo;
                unsigned w = __shfl_sync(0xFFFFFFFFu, rp, pp >> 1);
                int ki = (int)((w >> (16 * (pp & 1))) & 0xFFFFu);
                int kil = ki - cb;               // in [0, MCH)
                const float4* Kr = (const float4*)(Ks + (kil << 6));
                float4 a0 = Kr[h], a1 = Kr[h + 8];
                float e0 = qa.x * a0.x;          // two independent chains
                float e1 = qb.x * a1.x;
                e0 = fmaf(qa.y, a0.y, e0);
                e1 = fmaf(qb.y, a1.y, e1);
                e0 = fmaf(qa.z, a0.z, e0);
                e1 = fmaf(qb.z, a1.z, e1);
                e0 = fmaf(qa.w, a0.w, e0);
                e1 = fmaf(qb.w, a1.w, e1);
                float d = e0 + e1;
                d += __shfl_xor_sync(0xFFFFFFFFu, d, 1);
                d += __shfl_xor_sync(0xFFFFFFFFu, d, 2);
                d += __shfl_xor_sync(0xFFFFFFFFu, d, 4);
                if (act) { mxq = fmaxf(mxq, d); smq += d; }
            }
            mxq = fmaxf(mxq, __shfl_xor_sync(0xFFFFFFFFu, mxq, 8));
            mxq = fmaxf(mxq, __shfl_xor_sync(0xFFFFFFFFu, mxq, 16));
            smq += __shfl_xor_sync(0xFFFFFFFFu, smq, 8);
            smq += __shfl_xor_sync(0xFFFFFFFFu, smq, 16);
            if (lane == i) { mxs = fmaxf(mxs, mxq); sms += smq; }
        }
    }

    if (lane < MQT / 32) {
        int q = qlo + warp * (MQT / 32) + lane;
        g_Mkey[bh * LSEQ + q] = f2key(mxs - sms * (1.0f / LSEQ));
    }
}

// ================= 4. top-40 per (b,h) via radix select =================
__global__ __launch_bounds__(256) void topk_kernel() {
    __shared__ unsigned skeys[LSEQ];
    __shared__ unsigned hist[256];
    __shared__ int ebuf[64];
    __shared__ unsigned s_prefix;
    __shared__ int s_remaining, s_cnt, s_eq;

    int bh = blockIdx.x, t = threadIdx.x;
    for (int i = t; i < LSEQ; i += 256)
        skeys[i] = g_Mkey[bh * LSEQ + i];
    if (t == 0) { s_prefix = 0u; s_remaining = USEL; s_cnt = 0; s_eq = 0; }
    __syncthreads();

    const unsigned himask[4] = {0u, 0xFF000000u, 0xFFFF0000u, 0xFFFFFF00u};
#pragma unroll
    for (int r = 0; r < 4; r++) {
        int shift = 24 - 8 * r;
        hist[t] = 0;
        __syncthreads();
        unsigned pfx = s_prefix;
        for (int i = t; i < LSEQ; i += 256) {
            unsigned k = skeys[i];
            if ((k & himask[r]) == pfx)
                atomicAdd(&hist[(k >> shift) & 255u], 1u);
        }
        __syncthreads();
        if (t < 32) {
            unsigned v[8], tot = 0;
#pragma unroll
            for (int c = 0; c < 8; c++) { v[c] = hist[t * 8 + c]; tot += v[c]; }
            unsigned suf = tot;
#pragma unroll
            for (int off = 1; off < 32; off <<= 1) {
                unsigned o = __shfl_down_sync(0xFFFFFFFFu, suf, off);
                if (t + off < 32) suf += o;
            }
            unsigned below = suf - tot;
            int rem = s_remaining;
#pragma unroll
            for (int c = 7; c >= 0; c--) {
                unsigned here = below + v[c];
                if ((int)here >= rem && (int)below < rem) {
                    s_prefix = pfx | ((unsigned)(t * 8 + c) << shift);
                    s_remaining = rem - (int)below;
                }
                below = here;
            }
        }
        __syncthreads();
    }

    unsigned T = s_prefix;
    int need_eq = s_remaining;

    for (int i = t; i < LSEQ; i += 256) {
        unsigned k = skeys[i];
        if (k > T) {
            int p = atomicAdd(&s_cnt, 1);
            g_topk[bh * USEL + p] = i;
        } else if (k == T) {
            int p = atomicAdd(&s_eq, 1);
            if (p < 64) ebuf[p] = i;
        }
    }
    __syncthreads();

    int cnt_gt = s_cnt, cnt_eq = s_eq;
    if (cnt_eq == need_eq) {
        if (t < cnt_eq)
            g_topk[bh * USEL + cnt_gt + t] = ebuf[t];
    } else if (t == 0) {
        if (cnt_eq <= 64) {
            for (int n = 0; n < need_eq; n++) {
                int bi = -1, bv = LSEQ;
                for (int j = 0; j < cnt_eq; j++)
                    if (ebuf[j] < bv) { bv = ebuf[j]; bi = j; }
                g_topk[bh * USEL + cnt_gt + n] = bv;
                ebuf[bi] = LSEQ;
            }
        } else {
            int n = 0;
            for (int i = 0; i < LSEQ && n < need_eq; i++)
                if (skeys[i] == T) g_topk[bh * USEL + cnt_gt + n++] = i;
        }
    }
}

// ================= 5. attention partials: one 64-key tile per block ==========
// Block (ch 0..31, bh). Warp i owns queries {i+8a}; lane j owns keys/dims
// {j, j+32}. Single tile -> plain (non-online) softmax partials in registers.
__global__ __launch_bounds__(256) void attn_kernel(const float* __restrict__ Q,
                                                   const float* __restrict__ K,
                                                   const float* __restrict__ V) {
    extern __shared__ float sm[];
    float* Qs = sm + A_QS;               // USEL*64, pre-scaled Q
    float* Ks = sm + A_KS;               // 64 x KVS
    float* Vs = sm + A_VS;               // 64 x KVS
    float* Pt = sm + A_PT;               // 8 warps x 5 x 64 (warp-private)

    int ch = blockIdx.x, bh = blockIdx.y;
    int t = threadIdx.x;
    int i = t >> 5, j = t & 31;
    int kb = ch * CHK;

    const float* Kb = K + (size_t)bh * LSEQ * DIM;
    const float* Vb = V + (size_t)bh * LSEQ * DIM;

    for (int e = t; e < USEL * DIM; e += 256) {
        int q = e >> 6, d = e & 63;
        int qi = g_topk[bh * USEL + q];
        Qs[e] = Q[((size_t)bh * LSEQ + qi) * DIM + d] * 0.125f;
    }
#pragma unroll
    for (int rr = 0; rr < 4; rr++) {
        int f = t + rr * 256;
        int r = f >> 4, c4 = f & 15;
        *(float4*)&Ks[r * KVS + c4 * 4] =
            __ldg((const float4*)(Kb + (size_t)(kb + r) * DIM) + c4);
        *(float4*)&Vs[r * KVS + c4 * 4] =
            __ldg((const float4*)(Vb + (size_t)(kb + r) * DIM) + c4);
    }
    __syncthreads();

    // --- S = Qs @ K^T (registers) ---
    float s0[5], s1[5];
#pragma unroll
    for (int a = 0; a < 5; a++) { s0[a] = 0.f; s1[a] = 0.f; }
#pragma unroll
    for (int d4 = 0; d4 < 16; d4++) {
        float4 k0 = *(const float4*)&Ks[j * KVS + d4 * 4];
        float4 k1 = *(const float4*)&Ks[(j + 32) * KVS + d4 * 4];
#pragma unroll
        for (int a = 0; a < 5; a++) {
            float4 qv = *(const float4*)&Qs[(i + 8 * a) * 64 + d4 * 4];
            float u0 = s0[a];
            u0 = fmaf(qv.x, k0.x, u0);
            u0 = fmaf(qv.y, k0.y, u0);
            u0 = fmaf(qv.z, k0.z, u0);
            u0 = fmaf(qv.w, k0.w, u0);
            s0[a] = u0;
            float u1 = s1[a];
            u1 = fmaf(qv.x, k1.x, u1);
            u1 = fmaf(qv.y, k1.y, u1);
            u1 = fmaf(qv.z, k1.z, u1);
            u1 = fmaf(qv.w, k1.w, u1);
            s1[a] = u1;
        }
    }

    // --- tile softmax partials (registers, butterflies converge all lanes) ---
    float m_[5], l_[5], acc[5][2];
#pragma unroll
    for (int a = 0; a < 5; a++) {
        float tm = fmaxf(s0[a], s1[a]);
#pragma unroll
        for (int o = 16; o; o >>= 1)
            tm = fmaxf(tm, __shfl_xor_sync(0xFFFFFFFFu, tm, o));
        float p0 = __expf(s0[a] - tm);
        float p1 = __expf(s1[a] - tm);
        float su = p0 + p1;
#pragma unroll
        for (int o = 16; o; o >>= 1)
            su += __shfl_xor_sync(0xFFFFFFFFu, su, o);
        m_[a] = tm;
        l_[a] = su;
        acc[a][0] = 0.f;
        acc[a][1] = 0.f;
        Pt[(i * 5 + a) * 64 + j]      = p0;
        Pt[(i * 5 + a) * 64 + j + 32] = p1;
    }
    __syncwarp();                          // Pt is warp-private

    // --- acc = P @ V ---
#pragma unroll
    for (int k4 = 0; k4 < 16; k4++) {
        int k = k4 * 4;
        float v00 = Vs[(k + 0) * KVS + j];
        float v01 = Vs[(k + 1) * KVS + j];
        float v02 = Vs[(k + 2) * KVS + j];
        float v03 = Vs[(k + 3) * KVS + j];
        float v10 = Vs[(k + 0) * KVS + j + 32];
        float v11 = Vs[(k + 1) * KVS + j + 32];
        float v12 = Vs[(k + 2) * KVS + j + 32];
        float v13 = Vs[(k + 3) * KVS + j + 32];
#pragma unroll
        for (int a = 0; a < 5; a++) {
            float4 p = *(const float4*)&Pt[(i * 5 + a) * 64 + k];  // broadcast
            float u0 = acc[a][0];
            u0 = fmaf(p.x, v00, u0);
            u0 = fmaf(p.y, v01, u0);
            u0 = fmaf(p.z, v02, u0);
            u0 = fmaf(p.w, v03, u0);
            acc[a][0] = u0;
            float u1 = acc[a][1];
            u1 = fmaf(p.x, v10, u1);
            u1 = fmaf(p.y, v11, u1);
            u1 = fmaf(p.z, v12, u1);
            u1 = fmaf(p.w, v13, u1);
            acc[a][1] = u1;
        }
    }

    float* pa = g_pacc + (size_t)(bh * NCH + ch) * USEL * DIM;
#pragma unroll
    for (int a = 0; a < 5; a++) {
        int q = i + 8 * a;
        pa[q * DIM + j]      = acc[a][0];
        pa[q * DIM + j + 32] = acc[a][1];
    }
    if (j == 0) {
#pragma unroll
        for (int a = 0; a < 5; a++) {
            g_pm[(bh * NCH + ch) * USEL + i + 8 * a] = m_[a];
            g_pl[(bh * NCH + ch) * USEL + i + 8 * a] = l_[a];
        }
    }
}

// ================= 6. merge partials, scatter into output =================
__global__ void merge_kernel(float* __restrict__ out) {
    int u = blockIdx.x, bh = blockIdx.y, d = threadIdx.x;
    float M = -1e30f;
#pragma unroll
    for (int c = 0; c < NCH; c++)
        M = fmaxf(M, g_pm[(bh * NCH + c) * USEL + u]);
    float L = 0.f, o = 0.f;
#pragma unroll
    for (int c = 0; c < NCH; c++) {
        float w = __expf(g_pm[(bh * NCH + c) * USEL + u] - M);
        L += g_pl[(bh * NCH + c) * USEL + u] * w;
        o = fmaf(g_pacc[((size_t)(bh * NCH + c) * USEL + u) * DIM + d], w, o);
    }
    int qi = g_topk[bh * USEL + u];
    out[((size_t)bh * LSEQ + qi) * DIM + d] = o / L;
}

// ================= launcher =================
extern "C" void kernel_launch(void* const* d_in, const int* in_sizes, int n_in,
                              void* d_out, int out_size) {
    const float* Q    = (const float*)d_in[0];
    const float* K    = (const float*)d_in[1];
    const float* V    = (const float*)d_in[2];
    const int*   idxs = (const int*)d_in[3];
    float* out = (float*)d_out;
    int u = in_sizes[3] / LSEQ;   // 40

    cudaFuncSetAttribute(m_kernel, cudaFuncAttributeMaxDynamicSharedMemorySize, M_SMEM);
    cudaFuncSetAttribute(attn_kernel, cudaFuncAttributeMaxDynamicSharedMemorySize, A_SMEM);

    mean_kernel<<<BH, 1024>>>(V);
    fill_kernel<<<(BH * LSEQ * 16) / 256, 256>>>((float4*)out);
    sort_kernel<<<LSEQ / 256, 256>>>(idxs, u);
    m_kernel<<<dim3(LSEQ / MQT, BH), 1024, M_SMEM>>>(Q, K);
    topk_kernel<<<BH, 256>>>();
    attn_kernel<<<dim3(NCH, BH), 256, A_SMEM>>>(Q, K, V);
    merge_kernel<<<dim3(USEL, BH), 64>>>(out);
}

// round 8
// speedup vs baseline: 1.2921x; 1.0639x over previous
#include <cuda_runtime.h>
#include <cuda_bf16.h>
#include <math.h>

// Problem constants (fixed bench shapes)
#define BH    32            // B*H = 4*8
#define LSEQ  2048          // sequence length
#define DIM   64            // head dim
#define USEL  40            // u = U_part
#define NCH   32            // key chunks for split-softmax attention
#define CHK   (LSEQ/NCH)    // 64 keys per chunk (single tile per block)
#define KVS   68            // padded smem row stride for attn K/V tiles
#define MCH   512           // m_kernel key-chunk size
#define MQT   512           // m_kernel q-tile (4 tiles x 32 bh = 128 blocks, 1 wave)

// m_kernel smem layout (bytes)
#define MS_K     0                                   // 512*64*4   = 131072
#define MS_IDX   (MCH * DIM * 4)                     // +512*40*2  =  40960
#define MS_OFF   (MS_IDX + MQT * USEL * 2)           // +512*4     =   2048
#define M_SMEM   (MS_OFF + MQT * 4)                  // 174080 B (170 KB)

#define A_QS    0
#define A_KS    (USEL * DIM)
#define A_VS    (A_KS + 64 * KVS)
#define A_PT    (A_VS + 64 * KVS)
#define A_SMEM  ((A_PT + 8 * 5 * 64) * 4)            // 55,296 B

// -------- scratch (device globals; no allocation allowed) --------
__device__ unsigned g_Mkey[BH * LSEQ];
__device__ int   g_topk[BH * USEL];
__device__ float g_meanV[BH * DIM];
__device__ float g_pm[BH * NCH * USEL];
__device__ float g_pl[BH * NCH * USEL];
__device__ float g_pacc[(size_t)BH * NCH * USEL * DIM];   // 10.5 MB
__device__ unsigned short g_sidx[LSEQ * USEL];      // chunk-sorted, PRE-MASKED local idx
__device__ unsigned g_soff[LSEQ];                   // packed chunk start offsets

__device__ __forceinline__ unsigned f2key(float x) {
    unsigned k = __float_as_uint(x);
    return (k & 0x80000000u) ? ~k : (k | 0x80000000u);
}

// ================= 1. mean of V per (b,h): vectorized =================
__global__ __launch_bounds__(1024) void mean_kernel(const float* __restrict__ V) {
    __shared__ float4 sb[64][16];
    int bh = blockIdx.x, t = threadIdx.x;
    int part = t >> 4, c4 = t & 15;
    const float4* Vb = (const float4*)(V + (size_t)bh * LSEQ * DIM);
    float4 s = make_float4(0.f, 0.f, 0.f, 0.f);
    for (int l = part; l < LSEQ; l += 64) {
        float4 v = __ldg(Vb + l * 16 + c4);
        s.x += v.x; s.y += v.y; s.z += v.z; s.w += v.w;
    }
    sb[part][c4] = s;
    __syncthreads();
#pragma unroll
    for (int o = 32; o; o >>= 1) {
        if (part < o) {
            float4 a = sb[part][c4], b = sb[part + o][c4];
            a.x += b.x; a.y += b.y; a.z += b.z; a.w += b.w;
            sb[part][c4] = a;
        }
        __syncthreads();
    }
    if (t < 16) {
        float4 a = sb[0][t];
        a.x *= (1.0f / LSEQ); a.y *= (1.0f / LSEQ);
        a.z *= (1.0f / LSEQ); a.w *= (1.0f / LSEQ);
        ((float4*)g_meanV)[bh * 16 + t] = a;
    }
}

// ================= 2. broadcast-fill output with meanV =================
__global__ void fill_kernel(float4* __restrict__ out) {
    int i = blockIdx.x * blockDim.x + threadIdx.x;
    int bh = i >> 15;
    int d4 = i & 15;
    out[i] = ((const float4*)g_meanV)[bh * 16 + d4];
}

// ================= 2b. bucket samples by key-chunk; store LOCAL idx ==========
__global__ void sort_kernel(const int* __restrict__ idxs, int u) {
    int q = blockIdx.x * blockDim.x + threadIdx.x;
    if (q >= LSEQ) return;
    const int* ip = idxs + (size_t)q * u;
    int cnt[4] = {0, 0, 0, 0};
#pragma unroll
    for (int s = 0; s < USEL; s++)
        cnt[__ldg(ip + s) >> 9]++;
    int st1 = cnt[0];
    int st2 = st1 + cnt[1];
    int st3 = st2 + cnt[2];
    g_soff[q] = (unsigned)st1 | ((unsigned)st2 << 8) | ((unsigned)st3 << 16);
    int pos[4] = {0, st1, st2, st3};
#pragma unroll
    for (int s = 0; s < USEL; s++) {
        int ki = __ldg(ip + s);
        int c = ki >> 9;
        g_sidx[q * USEL + pos[c]++] = (unsigned short)(ki & (MCH - 1));
    }
}

// ================= 3. M scores: chunked, smem-resident K + smem idx lists =====
// Block = (q-tile of 512, bh), 1024 threads, 170 KB smem (1 block/SM, 1 wave).
// Index lists staged in smem as pre-masked uint16: per-sample cost is one
// broadcast LDS.U16 + IMAD (was SHFL+extract+SUB+IMAD). Dots: 8-lane groups,
// two 4-FMA chains, 3-shuffle reduce.
__global__ __launch_bounds__(1024, 1) void m_kernel(const float* __restrict__ Q,
                                                    const float* __restrict__ K) {
    extern __shared__ float smf[];
    float* Ks = smf;                                         // MCH x 64
    unsigned short* sIdx = (unsigned short*)((char*)smf + MS_IDX);
    unsigned* sOff = (unsigned*)((char*)smf + MS_OFF);

    int t = threadIdx.x, lane = t & 31, warp = t >> 5;
    int g = lane >> 3, h = lane & 7;
    int bh = blockIdx.y;
    int qlo = blockIdx.x * MQT;

    // stage this q-tile's index lists (40 KB) and offsets (2 KB)
    {
        const uint4* src = (const uint4*)(g_sidx + (size_t)qlo * USEL);
        uint4* dst = (uint4*)sIdx;
        for (int f = t; f < (MQT * USEL * 2) / 16; f += 1024)
            dst[f] = __ldg(src + f);
        if (t < MQT) sOff[t] = g_soff[qlo + t];
    }

    const float* Kb = K + (size_t)bh * LSEQ * DIM;
    float mxs = -1e30f, sms = 0.f;

    for (int c = 0; c < LSEQ / MCH; c++) {
        int cb = c * MCH;
        __syncthreads();   // previous chunk fully consumed (also covers idx staging)
#pragma unroll
        for (int k = 0; k < (MCH * 16) / 1024; k++) {
            int f = t + k * 1024;
            ((float4*)Ks)[f] = __ldg((const float4*)(Kb + (size_t)cb * DIM) + f);
        }
        __syncthreads();

        for (int i = 0; i < MQT / 32; i++) {          // 16 queries per warp
            int ql = warp * (MQT / 32) + i;
            int q = qlo + ql;
            unsigned sw = sOff[ql];
            int lo = c ? (int)((sw >> (8 * (c - 1))) & 255u) : 0;
            int hi = (c < 3) ? (int)((sw >> (8 * c)) & 255u) : USEL;

            const unsigned short* sq = sIdx + ql * USEL;
            const float4* Q4 = (const float4*)(Q + ((size_t)bh * LSEQ + q) * DIM);
            float4 qa = __ldg(Q4 + h);
            float4 qb = __ldg(Q4 + h + 8);

            float mxq = -1e30f, smq = 0.f;
#pragma unroll 2
            for (int p0 = lo; p0 < hi; p0 += 4) {
                int p = p0 + g;
                bool act = p < hi;
                int kil = sq[min(p, hi - 1)];    // broadcast LDS.U16
                const float4* Kr = (const float4*)(Ks + (kil << 6));
                float4 a0 = Kr[h], a1 = Kr[h + 8];
                float e0 = qa.x * a0.x;          // two independent chains
                float e1 = qb.x * a1.x;
                e0 = fmaf(qa.y, a0.y, e0);
                e1 = fmaf(qb.y, a1.y, e1);
                e0 = fmaf(qa.z, a0.z, e0);
                e1 = fmaf(qb.z, a1.z, e1);
                e0 = fmaf(qa.w, a0.w, e0);
                e1 = fmaf(qb.w, a1.w, e1);
                float d = e0 + e1;
                d += __shfl_xor_sync(0xFFFFFFFFu, d, 1);
                d += __shfl_xor_sync(0xFFFFFFFFu, d, 2);
                d += __shfl_xor_sync(0xFFFFFFFFu, d, 4);
                if (act) { mxq = fmaxf(mxq, d); smq += d; }
            }
            mxq = fmaxf(mxq, __shfl_xor_sync(0xFFFFFFFFu, mxq, 8));
            mxq = fmaxf(mxq, __shfl_xor_sync(0xFFFFFFFFu, mxq, 16));
            smq += __shfl_xor_sync(0xFFFFFFFFu, smq, 8);
            smq += __shfl_xor_sync(0xFFFFFFFFu, smq, 16);
            if (lane == i) { mxs = fmaxf(mxs, mxq); sms += smq; }
        }
    }

    if (lane < MQT / 32) {
        int q = qlo + warp * (MQT / 32) + lane;
        g_Mkey[bh * LSEQ + q] = f2key(mxs - sms * (1.0f / LSEQ));
    }
}

// ================= 4. top-40 per (b,h) via radix select (512 threads) ========
__global__ __launch_bounds__(512) void topk_kernel() {
    __shared__ unsigned skeys[LSEQ];
    __shared__ unsigned hist[256];
    __shared__ int ebuf[64];
    __shared__ unsigned s_prefix;
    __shared__ int s_remaining, s_cnt, s_eq;

    int bh = blockIdx.x, t = threadIdx.x;
    for (int i = t; i < LSEQ; i += 512)
        skeys[i] = g_Mkey[bh * LSEQ + i];
    if (t == 0) { s_prefix = 0u; s_remaining = USEL; s_cnt = 0; s_eq = 0; }
    __syncthreads();

    const unsigned himask[4] = {0u, 0xFF000000u, 0xFFFF0000u, 0xFFFFFF00u};
#pragma unroll
    for (int r = 0; r < 4; r++) {
        int shift = 24 - 8 * r;
        if (t < 256) hist[t] = 0;
        __syncthreads();
        unsigned pfx = s_prefix;
        for (int i = t; i < LSEQ; i += 512) {
            unsigned k = skeys[i];
            if ((k & himask[r]) == pfx)
                atomicAdd(&hist[(k >> shift) & 255u], 1u);
        }
        __syncthreads();
        if (t < 32) {
            unsigned v[8], tot = 0;
#pragma unroll
            for (int c = 0; c < 8; c++) { v[c] = hist[t * 8 + c]; tot += v[c]; }
            unsigned suf = tot;
#pragma unroll
            for (int off = 1; off < 32; off <<= 1) {
                unsigned o = __shfl_down_sync(0xFFFFFFFFu, suf, off);
                if (t + off < 32) suf += o;
            }
            unsigned below = suf - tot;
            int rem = s_remaining;
#pragma unroll
            for (int c = 7; c >= 0; c--) {
                unsigned here = below + v[c];
                if ((int)here >= rem && (int)below < rem) {
                    s_prefix = pfx | ((unsigned)(t * 8 + c) << shift);
                    s_remaining = rem - (int)below;
                }
                below = here;
            }
        }
        __syncthreads();
    }

    unsigned T = s_prefix;
    int need_eq = s_remaining;

    for (int i = t; i < LSEQ; i += 512) {
        unsigned k = skeys[i];
        if (k > T) {
            int p = atomicAdd(&s_cnt, 1);
            g_topk[bh * USEL + p] = i;
        } else if (k == T) {
            int p = atomicAdd(&s_eq, 1);
            if (p < 64) ebuf[p] = i;
        }
    }
    __syncthreads();

    int cnt_gt = s_cnt, cnt_eq = s_eq;
    if (cnt_eq == need_eq) {
        if (t < cnt_eq)
            g_topk[bh * USEL + cnt_gt + t] = ebuf[t];
    } else if (t == 0) {
        if (cnt_eq <= 64) {
            for (int n = 0; n < need_eq; n++) {
                int bi = -1, bv = LSEQ;
                for (int j = 0; j < cnt_eq; j++)
                    if (ebuf[j] < bv) { bv = ebuf[j]; bi = j; }
                g_topk[bh * USEL + cnt_gt + n] = bv;
                ebuf[bi] = LSEQ;
            }
        } else {
            int n = 0;
            for (int i = 0; i < LSEQ && n < need_eq; i++)
                if (skeys[i] == T) g_topk[bh * USEL + cnt_gt + n++] = i;
        }
    }
}

// ================= 5. attention partials: one 64-key tile per block ==========
__global__ __launch_bounds__(256) void attn_kernel(const float* __restrict__ Q,
                                                   const float* __restrict__ K,
                                                   const float* __restrict__ V) {
    extern __shared__ float sm[];
    float* Qs = sm + A_QS;
    float* Ks = sm + A_KS;
    float* Vs = sm + A_VS;
    float* Pt = sm + A_PT;

    int ch = blockIdx.x, bh = blockIdx.y;
    int t = threadIdx.x;
    int i = t >> 5, j = t & 31;
    int kb = ch * CHK;

    const float* Kb = K + (size_t)bh * LSEQ * DIM;
    const float* Vb = V + (size_t)bh * LSEQ * DIM;

    for (int e = t; e < USEL * DIM; e += 256) {
        int q = e >> 6, d = e & 63;
        int qi = g_topk[bh * USEL + q];
        Qs[e] = Q[((size_t)bh * LSEQ + qi) * DIM + d] * 0.125f;
    }
#pragma unroll
    for (int rr = 0; rr < 4; rr++) {
        int f = t + rr * 256;
        int r = f >> 4, c4 = f & 15;
        *(float4*)&Ks[r * KVS + c4 * 4] =
            __ldg((const float4*)(Kb + (size_t)(kb + r) * DIM) + c4);
        *(float4*)&Vs[r * KVS + c4 * 4] =
            __ldg((const float4*)(Vb + (size_t)(kb + r) * DIM) + c4);
    }
    __syncthreads();

    float s0[5], s1[5];
#pragma unroll
    for (int a = 0; a < 5; a++) { s0[a] = 0.f; s1[a] = 0.f; }
#pragma unroll
    for (int d4 = 0; d4 < 16; d4++) {
        float4 k0 = *(const float4*)&Ks[j * KVS + d4 * 4];
        float4 k1 = *(const float4*)&Ks[(j + 32) * KVS + d4 * 4];
#pragma unroll
        for (int a = 0; a < 5; a++) {
            float4 qv = *(const float4*)&Qs[(i + 8 * a) * 64 + d4 * 4];
            float u0 = s0[a];
            u0 = fmaf(qv.x, k0.x, u0);
            u0 = fmaf(qv.y, k0.y, u0);
            u0 = fmaf(qv.z, k0.z, u0);
            u0 = fmaf(qv.w, k0.w, u0);
            s0[a] = u0;
            float u1 = s1[a];
            u1 = fmaf(qv.x, k1.x, u1);
            u1 = fmaf(qv.y, k1.y, u1);
            u1 = fmaf(qv.z, k1.z, u1);
            u1 = fmaf(qv.w, k1.w, u1);
            s1[a] = u1;
        }
    }

    float m_[5], l_[5], acc[5][2];
#pragma unroll
    for (int a = 0; a < 5; a++) {
        float tm = fmaxf(s0[a], s1[a]);
#pragma unroll
        for (int o = 16; o; o >>= 1)
            tm = fmaxf(tm, __shfl_xor_sync(0xFFFFFFFFu, tm, o));
        float p0 = __expf(s0[a] - tm);
        float p1 = __expf(s1[a] - tm);
        float su = p0 + p1;
#pragma unroll
        for (int o = 16; o; o >>= 1)
            su += __shfl_xor_sync(0xFFFFFFFFu, su, o);
        m_[a] = tm;
        l_[a] = su;
        acc[a][0] = 0.f;
        acc[a][1] = 0.f;
        Pt[(i * 5 + a) * 64 + j]      = p0;
        Pt[(i * 5 + a) * 64 + j + 32] = p1;
    }
    __syncwarp();

#pragma unroll
    for (int k4 = 0; k4 < 16; k4++) {
        int k = k4 * 4;
        float v00 = Vs[(k + 0) * KVS + j];
        float v01 = Vs[(k + 1) * KVS + j];
        float v02 = Vs[(k + 2) * KVS + j];
        float v03 = Vs[(k + 3) * KVS + j];
        float v10 = Vs[(k + 0) * KVS + j + 32];
        float v11 = Vs[(k + 1) * KVS + j + 32];
        float v12 = Vs[(k + 2) * KVS + j + 32];
        float v13 = Vs[(k + 3) * KVS + j + 32];
#pragma unroll
        for (int a = 0; a < 5; a++) {
            float4 p = *(const float4*)&Pt[(i * 5 + a) * 64 + k];
            float u0 = acc[a][0];
            u0 = fmaf(p.x, v00, u0);
            u0 = fmaf(p.y, v01, u0);
            u0 = fmaf(p.z, v02, u0);
            u0 = fmaf(p.w, v03, u0);
            acc[a][0] = u0;
            float u1 = acc[a][1];
            u1 = fmaf(p.x, v10, u1);
            u1 = fmaf(p.y, v11, u1);
            u1 = fmaf(p.z, v12, u1);
            u1 = fmaf(p.w, v13, u1);
            acc[a][1] = u1;
        }
    }

    float* pa = g_pacc + (size_t)(bh * NCH + ch) * USEL * DIM;
#pragma unroll
    for (int a = 0; a < 5; a++) {
        int q = i + 8 * a;
        pa[q * DIM + j]      = acc[a][0];
        pa[q * DIM + j + 32] = acc[a][1];
    }
    if (j == 0) {
#pragma unroll
        for (int a = 0; a < 5; a++) {
            g_pm[(bh * NCH + ch) * USEL + i + 8 * a] = m_[a];
            g_pl[(bh * NCH + ch) * USEL + i + 8 * a] = l_[a];
        }
    }
}

// ================= 6. merge partials, scatter into output =================
__global__ void merge_kernel(float* __restrict__ out) {
    int u = blockIdx.x, bh = blockIdx.y, d = threadIdx.x;
    float M = -1e30f;
#pragma unroll
    for (int c = 0; c < NCH; c++)
        M = fmaxf(M, g_pm[(bh * NCH + c) * USEL + u]);
    float L = 0.f, o = 0.f;
#pragma unroll
    for (int c = 0; c < NCH; c++) {
        float w = __expf(g_pm[(bh * NCH + c) * USEL + u] - M);
        L += g_pl[(bh * NCH + c) * USEL + u] * w;
        o = fmaf(g_pacc[((size_t)(bh * NCH + c) * USEL + u) * DIM + d], w, o);
    }
    int qi = g_topk[bh * USEL + u];
    out[((size_t)bh * LSEQ + qi) * DIM + d] = o / L;
}

// ================= launcher =================
extern "C" void kernel_launch(void* const* d_in, const int* in_sizes, int n_in,
                              void* d_out, int out_size) {
    const float* Q    = (const float*)d_in[0];
    const float* K    = (const float*)d_in[1];
    const float* V    = (const float*)d_in[2];
    const int*   idxs = (const int*)d_in[3];
    float* out = (float*)d_out;
    int u = in_sizes[3] / LSEQ;   // 40

    cudaFuncSetAttribute(m_kernel, cudaFuncAttributeMaxDynamicSharedMemorySize, M_SMEM);
    cudaFuncSetAttribute(attn_kernel, cudaFuncAttributeMaxDynamicSharedMemorySize, A_SMEM);

    mean_kernel<<<BH, 1024>>>(V);
    fill_kernel<<<(BH * LSEQ * 16) / 256, 256>>>((float4*)out);
    sort_kernel<<<LSEQ / 256, 256>>>(idxs, u);
    m_kernel<<<dim3(LSEQ / MQT, BH), 1024, M_SMEM>>>(Q, K);
    topk_kernel<<<BH, 512>>>();
    attn_kernel<<<dim3(NCH, BH), 256, A_SMEM>>>(Q, K, V);
    merge_kernel<<<dim3(USEL, BH), 64>>>(out);
}